// round 16
// baseline (speedup 1.0000x reference)
#include <cuda_runtime.h>
#include <cuda_fp16.h>
#include <cstdint>
#include <math.h>

// ---------------- problem constants ----------------
#define TOPK 6
#define NE   64
#define ND   2048
#define NF   1408
#define NFS  2816
#define NTOK 8192
#define NA   (NTOK*TOPK)   // 49152 routed assignments
#define CAP  1536

// ---------------- scratch (device globals) ----------------
__device__ int    g_counts[NE];
__device__ int    g_offsets[NE];
__device__ int    g_cursor[NE];
__device__ int    g_tidx[NA];
__device__ float  g_tw[NA];
__device__ int    g_stok[NA];
__device__ int    g_a2p[NA];
__device__ __half g_xh[(size_t)NTOK * ND];   // x in fp16
__device__ __half g_u [(size_t)NA * NF];     // up proj then act, fp16
__device__ __half g_eo[(size_t)NA * ND];     // expert output rows, fp16
__device__ __half g_su[(size_t)NTOK * NFS];  // shared up then act, fp16
// fp16 weight mirrors
__device__ __half g_wu_h[(size_t)NE * NF * ND];
__device__ __half g_wg_h[(size_t)NE * NF * ND];
__device__ __half g_wd_h[(size_t)NE * ND * NF];
__device__ __half g_shu_h[(size_t)NFS * ND];
__device__ __half g_shg_h[(size_t)NFS * ND];
__device__ __half g_shd_h[(size_t)ND * NFS];

// ---------------- small kernels ----------------
__global__ void zero_kernel() {
    int i = threadIdx.x;
    if (i < NE) { g_counts[i] = 0; g_cursor[i] = 0; }
}

// fp32 -> fp16, 16 elems/thread (4x LDG.128 -> 2x STG.128)
__global__ void cvt_kernel(const float* __restrict__ w, __half* __restrict__ o) {
    size_t i = ((size_t)blockIdx.x * blockDim.x + threadIdx.x) * 16;
    float4 v0 = *(const float4*)(w + i);
    float4 v1 = *(const float4*)(w + i + 4);
    float4 v2 = *(const float4*)(w + i + 8);
    float4 v3 = *(const float4*)(w + i + 12);
    __half2 h0 = __floats2half2_rn(v0.x, v0.y);
    __half2 h1 = __floats2half2_rn(v0.z, v0.w);
    __half2 h2 = __floats2half2_rn(v1.x, v1.y);
    __half2 h3 = __floats2half2_rn(v1.z, v1.w);
    __half2 h4 = __floats2half2_rn(v2.x, v2.y);
    __half2 h5 = __floats2half2_rn(v2.z, v2.w);
    __half2 h6 = __floats2half2_rn(v3.x, v3.y);
    __half2 h7 = __floats2half2_rn(v3.z, v3.w);
    *(uint4*)&o[i]     = make_uint4(*(unsigned*)&h0, *(unsigned*)&h1,
                                    *(unsigned*)&h2, *(unsigned*)&h3);
    *(uint4*)&o[i + 8] = make_uint4(*(unsigned*)&h4, *(unsigned*)&h5,
                                    *(unsigned*)&h6, *(unsigned*)&h7);
}

__global__ void router_kernel(const float* __restrict__ x,
                              const float* __restrict__ gw)
{
    int t = blockIdx.x;
    __shared__ float xs[ND];
    __shared__ float logits[NE];
    const float* xr = x + (size_t)t * ND;
    for (int i = threadIdx.x; i < ND; i += blockDim.x) xs[i] = xr[i];
    __syncthreads();

    int warp = threadIdx.x >> 5, lane = threadIdx.x & 31;
    #pragma unroll
    for (int e8 = 0; e8 < 8; e8++) {
        int e = warp * 8 + e8;
        const float* w = gw + (size_t)e * ND;
        float s = 0.f;
        for (int i = lane; i < ND; i += 32) s += xs[i] * w[i];
        #pragma unroll
        for (int o = 16; o; o >>= 1) s += __shfl_down_sync(0xffffffffu, s, o);
        if (lane == 0) logits[e] = s;
    }
    __syncthreads();

    if (threadIdx.x == 0) {
        int idx6[TOPK]; float val6[TOPK];
        unsigned long long used = 0ull;
        for (int k = 0; k < TOPK; k++) {
            float best = -INFINITY; int bi = 0;
            for (int e = 0; e < NE; e++) {
                if (!((used >> e) & 1ull) && logits[e] > best) { best = logits[e]; bi = e; }
            }
            used |= 1ull << bi; idx6[k] = bi; val6[k] = best;
        }
        float m = val6[0], sum = 0.f, w6[TOPK];
        #pragma unroll
        for (int k = 0; k < TOPK; k++) { w6[k] = expf(val6[k] - m); sum += w6[k]; }
        float inv = 1.f / sum;
        #pragma unroll
        for (int k = 0; k < TOPK; k++) {
            g_tidx[t * TOPK + k] = idx6[k];
            g_tw  [t * TOPK + k] = w6[k] * inv;
            atomicAdd(&g_counts[idx6[k]], 1);
        }
    }
}

__global__ void prefix_kernel() {
    if (threadIdx.x == 0) {
        int acc = 0;
        for (int e = 0; e < NE; e++) { g_offsets[e] = acc; acc += g_counts[e]; }
    }
}

__global__ void scatter_kernel() {
    int a = blockIdx.x * blockDim.x + threadIdx.x;
    if (a >= NA) return;
    int e = g_tidx[a];
    int slot = atomicAdd(&g_cursor[e], 1);
    if (slot < CAP) {
        int p = g_offsets[e] + slot;
        g_stok[p] = a / TOPK;
        g_a2p[a] = p;
    } else {
        g_a2p[a] = -1;
    }
}

// ---------------- all-fp16 tensor-core GEMM (cp.async, BK=64, 3 stages) ------
// C[m][n] = sum_k A[m][k] * B[n][k]; A,B fp16; 128 threads, CTA 128x128,
// warp 64x64 (2x2), BK=64, 96KB dynamic smem, ldmatrix frag loads.
// Smem: full SW128 rows of 128B: off(row,h) = row*128 + ((h ^ (row&7))<<4).

__device__ __forceinline__ uint32_t smem_u32(const void* p) {
    uint32_t a;
    asm("{ .reg .u64 t; cvta.to.shared.u64 t, %1; cvt.u32.u64 %0, t; }" : "=r"(a) : "l"(p));
    return a;
}

__device__ __forceinline__ uint32_t swz(int row, int h) {
    return (uint32_t)((row << 7) + (((h ^ (row & 7))) << 4));
}

__device__ __forceinline__ void cp_async16(uint32_t saddr, const void* gptr) {
    asm volatile("cp.async.cg.shared.global [%0], [%1], 16;"
                 :: "r"(saddr), "l"(gptr));
}

__device__ __forceinline__ void ldsm4(unsigned& r0, unsigned& r1, unsigned& r2,
                                      unsigned& r3, uint32_t addr) {
    asm volatile("ldmatrix.sync.aligned.m8n8.x4.shared.b16 {%0,%1,%2,%3}, [%4];"
                 : "=r"(r0), "=r"(r1), "=r"(r2), "=r"(r3) : "r"(addr));
}

__device__ __forceinline__ void mma_f16(float d[4], const unsigned a[4],
                                        const unsigned b[2], const float c[4]) {
    asm volatile(
        "mma.sync.aligned.m16n8k16.row.col.f32.f16.f16.f32 "
        "{%0,%1,%2,%3},{%4,%5,%6,%7},{%8,%9},{%10,%11,%12,%13};\n"
        : "=f"(d[0]), "=f"(d[1]), "=f"(d[2]), "=f"(d[3])
        : "r"(a[0]), "r"(a[1]), "r"(a[2]), "r"(a[3]),
          "r"(b[0]), "r"(b[1]),
          "f"(c[0]), "f"(c[1]), "f"(c[2]), "f"(c[3]));
}

#define MAT_BYTES   16384           // 128 rows x 128B
#define STAGE_BYTES 32768           // A + B
#define NSTAGE      3
#define SMEM_GEMM   (NSTAGE * STAGE_BYTES)   // 98304

template<int OH, int FUSE>
__global__ __launch_bounds__(128)
void gemm16(const __half* __restrict__ A, int lda,
            const __half* __restrict__ B,
            void* __restrict__ Cv, int ldc,
            int M, int Ntot, int K,
            const int* __restrict__ rowmap,
            const int* __restrict__ offsets,
            const int* __restrict__ counts)
{
    extern __shared__ char sm[];

    int rowbase = 0;
    if (offsets) {
        int e = blockIdx.z;
        rowbase = offsets[e];
        M = min(counts[e], CAP);
        B += (size_t)e * Ntot * K;
    }
    int m0 = blockIdx.y * 128;
    if (m0 >= M) return;
    int n0 = blockIdx.x * 128;

    int tid = threadIdx.x, warp = tid >> 5, lane = tid & 31;
    int wm = warp >> 1, wn = warp & 1;
    int mb = wm * 64, nb = wn * 64;
    int grp = lane >> 2, tig = lane & 3;

    // ---- fill mapping: thread owns A row tid and B row tid (8x16B each) ----
    int arow = min(m0 + tid, M - 1);
    int phys = rowmap ? rowmap[rowbase + arow] : (rowbase + arow);
    const __half* ap = A + (size_t)phys * lda;
    const __half* bp = B + (size_t)(n0 + tid) * K;
    uint32_t strow[8];
    #pragma unroll
    for (int h = 0; h < 8; h++) strow[h] = swz(tid, h);

    // ---- ldmatrix lane mapping: 4 k-steps over 128B rows ----
    int lrow = (lane & 7) + 8 * ((lane >> 3) & 1);
    int lh = (lane >> 4) & 1;
    uint32_t sbase = smem_u32(sm);
    uint32_t loff[4];   // per-ks offset relative to matrix base, for row lrow
    #pragma unroll
    for (int ks = 0; ks < 4; ks++) loff[ks] = swz(lrow, 2 * ks + lh);

    float acc[4][8][4];
    #pragma unroll
    for (int mt = 0; mt < 4; mt++)
        #pragma unroll
        for (int nt = 0; nt < 8; nt++)
            #pragma unroll
            for (int j = 0; j < 4; j++) acc[mt][nt][j] = 0.f;

    const int nch = K / 64;

    auto fill = [&](int kc, int s) {
        uint32_t sa = sbase + s * STAGE_BYTES;
        uint32_t sb = sa + MAT_BYTES;
        #pragma unroll
        for (int h = 0; h < 8; h++) {
            cp_async16(sa + strow[h], ap + kc + h * 8);
            cp_async16(sb + strow[h], bp + kc + h * 8);
        }
        asm volatile("cp.async.commit_group;" ::: "memory");
    };

    // prolog: stages 0,1 <- chunks 0,1
    fill(0, 0);
    fill(64, 1);

    for (int it = 0; it < nch; it++) {
        int s = it % NSTAGE;
        if (it + 1 < nch)
            asm volatile("cp.async.wait_group 1;" ::: "memory");
        else
            asm volatile("cp.async.wait_group 0;" ::: "memory");
        __syncthreads();

        uint32_t sA = sbase + s * STAGE_BYTES;
        uint32_t sB = sA + MAT_BYTES;
        #pragma unroll
        for (int ks = 0; ks < 4; ks++) {
            unsigned af[4][4], bf[8][2];
            #pragma unroll
            for (int mt = 0; mt < 4; mt++)
                ldsm4(af[mt][0], af[mt][1], af[mt][2], af[mt][3],
                      sA + loff[ks] + (mb + mt * 16) * 128);
            #pragma unroll
            for (int np = 0; np < 4; np++) {
                unsigned t0, t1, t2, t3;
                ldsm4(t0, t1, t2, t3, sB + loff[ks] + (nb + np * 16) * 128);
                bf[2 * np][0] = t0;     bf[2 * np][1] = t2;
                bf[2 * np + 1][0] = t1; bf[2 * np + 1][1] = t3;
            }
            #pragma unroll
            for (int mt = 0; mt < 4; mt++)
                #pragma unroll
                for (int nt = 0; nt < 8; nt++)
                    mma_f16(acc[mt][nt], af[mt], bf[nt], acc[mt][nt]);
        }

        if (it + 2 < nch) fill((it + 2) * 64, (it + 2) % NSTAGE);
    }

    // ---- epilogue ----
    #pragma unroll
    for (int mt = 0; mt < 4; mt++) {
        int row0 = m0 + mb + mt * 16 + grp;
        #pragma unroll
        for (int nt = 0; nt < 8; nt++) {
            int col = n0 + nb + nt * 8 + tig * 2;
            #pragma unroll
            for (int h = 0; h < 2; h++) {
                int row = row0 + h * 8;
                if (row >= M) continue;
                float v0 = acc[mt][nt][2 * h], v1 = acc[mt][nt][2 * h + 1];
                if (OH) {
                    __half2* p = (__half2*)(((__half*)Cv) + (size_t)(rowbase + row) * ldc + col);
                    if (FUSE) {
                        float2 u = __half22float2(*p);
                        v0 = (v0 / (1.f + __expf(-v0))) * u.x;
                        v1 = (v1 / (1.f + __expf(-v1))) * u.y;
                    }
                    *p = __floats2half2_rn(v0, v1);
                } else {
                    float* p = ((float*)Cv) + (size_t)(rowbase + row) * ldc + col;
                    p[0] = v0; p[1] = v1;
                }
            }
        }
    }
}

// out[t][2d..2d+1] += sum_k w(t,k) * eo_h[pos(t,k)][2d..2d+1]
__global__ void combine_kernel(float* __restrict__ out) {
    int t = blockIdx.y;
    int d2 = blockIdx.x * blockDim.x + threadIdx.x;   // half2 index
    float2 s = *(float2*)&out[(size_t)t * ND + 2 * d2];
    #pragma unroll
    for (int k = 0; k < TOPK; k++) {
        int p = g_a2p[t * TOPK + k];
        if (p >= 0) {
            float w = g_tw[t * TOPK + k];
            __half2 h = *(__half2*)&g_eo[(size_t)p * ND + 2 * d2];
            float2 v = __half22float2(h);
            s.x += w * v.x; s.y += w * v.y;
        }
    }
    *(float2*)&out[(size_t)t * ND + 2 * d2] = s;
}

// ---------------- static stream/event resources (host-side only) ----------------
struct AuxRes {
    cudaStream_t s2, s3;
    cudaEvent_t ev_fork, ev_cvt, ev_wup, ev_wgate, ev_wdown, ev_shared;
    AuxRes() {
        cudaStreamCreateWithFlags(&s2, cudaStreamNonBlocking);
        cudaStreamCreateWithFlags(&s3, cudaStreamNonBlocking);
        cudaEventCreateWithFlags(&ev_fork,   cudaEventDisableTiming);
        cudaEventCreateWithFlags(&ev_cvt,    cudaEventDisableTiming);
        cudaEventCreateWithFlags(&ev_wup,    cudaEventDisableTiming);
        cudaEventCreateWithFlags(&ev_wgate,  cudaEventDisableTiming);
        cudaEventCreateWithFlags(&ev_wdown,  cudaEventDisableTiming);
        cudaEventCreateWithFlags(&ev_shared, cudaEventDisableTiming);
    }
};
static AuxRes g_aux;

// ---------------- launch ----------------
extern "C" void kernel_launch(void* const* d_in, const int* in_sizes, int n_in,
                              void* d_out, int out_size)
{
    const float* x       = (const float*)d_in[0];
    const float* gate_w  = (const float*)d_in[1];
    const float* w_gate  = (const float*)d_in[2];
    const float* w_up    = (const float*)d_in[3];
    const float* w_down  = (const float*)d_in[4];
    const float* sh_gate = (const float*)d_in[5];
    const float* sh_up   = (const float*)d_in[6];
    const float* sh_down = (const float*)d_in[7];
    float* out = (float*)d_out;

    void *pxh, *pu, *peo, *psu, *pstok, *poff, *pcnt;
    void *pwu, *pwg, *pwd, *pshu, *pshg, *pshd;
    cudaGetSymbolAddress(&pxh,  g_xh);
    cudaGetSymbolAddress(&pu,   g_u);
    cudaGetSymbolAddress(&peo,  g_eo);
    cudaGetSymbolAddress(&psu,  g_su);
    cudaGetSymbolAddress(&pstok, g_stok);
    cudaGetSymbolAddress(&poff, g_offsets);
    cudaGetSymbolAddress(&pcnt, g_counts);
    cudaGetSymbolAddress(&pwu,  g_wu_h);
    cudaGetSymbolAddress(&pwg,  g_wg_h);
    cudaGetSymbolAddress(&pwd,  g_wd_h);
    cudaGetSymbolAddress(&pshu, g_shu_h);
    cudaGetSymbolAddress(&pshg, g_shg_h);
    cudaGetSymbolAddress(&pshd, g_shd_h);
    __half* xh  = (__half*)pxh;
    __half* ubuf = (__half*)pu;  __half* eo = (__half*)peo;  __half* su = (__half*)psu;
    __half* wu_h = (__half*)pwu; __half* wg_h = (__half*)pwg; __half* wd_h = (__half*)pwd;
    __half* shu_h = (__half*)pshu; __half* shg_h = (__half*)pshg; __half* shd_h = (__half*)pshd;
    int* stok = (int*)pstok;     int* offs = (int*)poff;     int* cnts = (int*)pcnt;

    cudaStream_t s1 = 0;            // main (capture) stream
    cudaStream_t s2 = g_aux.s2;     // x cvt + shared-expert chain
    cudaStream_t s3 = g_aux.s3;     // routed weight conversions

    cudaFuncSetAttribute(gemm16<1,0>, cudaFuncAttributeMaxDynamicSharedMemorySize, SMEM_GEMM);
    cudaFuncSetAttribute(gemm16<1,1>, cudaFuncAttributeMaxDynamicSharedMemorySize, SMEM_GEMM);
    cudaFuncSetAttribute(gemm16<0,0>, cudaFuncAttributeMaxDynamicSharedMemorySize, SMEM_GEMM);

    const unsigned WBLK = (unsigned)((size_t)NE * NF * ND / 16 / 256);
    const unsigned SBLK = (unsigned)((size_t)NFS * ND / 16 / 256);
    const unsigned XBLK = (unsigned)((size_t)NTOK * ND / 16 / 256);

    // ---- fork ----
    cudaEventRecord(g_aux.ev_fork, s1);
    cudaStreamWaitEvent(s2, g_aux.ev_fork, 0);
    cudaStreamWaitEvent(s3, g_aux.ev_fork, 0);

    // ---- stream 3: routed weight conversions (start at t=0) ----
    cvt_kernel<<<WBLK, 256, 0, s3>>>(w_up, wu_h);
    cudaEventRecord(g_aux.ev_wup, s3);
    cvt_kernel<<<WBLK, 256, 0, s3>>>(w_gate, wg_h);
    cudaEventRecord(g_aux.ev_wgate, s3);
    cvt_kernel<<<WBLK, 256, 0, s3>>>(w_down, wd_h);
    cudaEventRecord(g_aux.ev_wdown, s3);

    // ---- stream 2: x cvt + shared weight cvts + shared-expert chain ----
    cvt_kernel<<<XBLK, 256, 0, s2>>>(x, xh);
    cudaEventRecord(g_aux.ev_cvt, s2);
    cvt_kernel<<<SBLK, 256, 0, s2>>>(sh_up,   shu_h);
    cvt_kernel<<<SBLK, 256, 0, s2>>>(sh_gate, shg_h);
    cvt_kernel<<<SBLK, 256, 0, s2>>>(sh_down, shd_h);
    {
        dim3 grid(NFS / 128, NTOK / 128, 1);
        gemm16<1,0><<<grid, 128, SMEM_GEMM, s2>>>(xh, ND, shu_h, su, NFS, NTOK, NFS, ND, nullptr, nullptr, nullptr);
        gemm16<1,1><<<grid, 128, SMEM_GEMM, s2>>>(xh, ND, shg_h, su, NFS, NTOK, NFS, ND, nullptr, nullptr, nullptr);
    }
    {
        dim3 grid(ND / 128, NTOK / 128, 1);
        gemm16<0,0><<<grid, 128, SMEM_GEMM, s2>>>(su, NFS, shd_h, out, ND, NTOK, ND, NFS, nullptr, nullptr, nullptr);
    }
    cudaEventRecord(g_aux.ev_shared, s2);

    // ---- stream 1: router + dispatch + routed chain ----
    zero_kernel<<<1, 64, 0, s1>>>();
    router_kernel<<<NTOK, 256, 0, s1>>>(x, gate_w);
    prefix_kernel<<<1, 1, 0, s1>>>();
    scatter_kernel<<<(NA + 255) / 256, 256, 0, s1>>>();

    cudaStreamWaitEvent(s1, g_aux.ev_cvt, 0);
    cudaStreamWaitEvent(s1, g_aux.ev_wup, 0);
    {
        dim3 grid(NF / 128, CAP / 128, NE);
        gemm16<1,0><<<grid, 128, SMEM_GEMM, s1>>>(xh, ND, wu_h, ubuf, NF, 0, NF, ND, stok, offs, cnts);
        cudaStreamWaitEvent(s1, g_aux.ev_wgate, 0);
        gemm16<1,1><<<grid, 128, SMEM_GEMM, s1>>>(xh, ND, wg_h, ubuf, NF, 0, NF, ND, stok, offs, cnts);
    }
    cudaStreamWaitEvent(s1, g_aux.ev_wdown, 0);
    {
        dim3 grid(ND / 128, CAP / 128, NE);
        gemm16<1,0><<<grid, 128, SMEM_GEMM, s1>>>(ubuf, NF, wd_h, eo, ND, 0, ND, NF, nullptr, offs, cnts);
    }

    // ---- join: combine needs shared-down (out) + routed-down (eo) ----
    cudaStreamWaitEvent(s1, g_aux.ev_shared, 0);
    {
        dim3 grid((ND / 2) / 256, NTOK);
        combine_kernel<<<grid, 256, 0, s1>>>(out);
    }
}

// round 17
// speedup vs baseline: 1.6268x; 1.6268x over previous
#include <cuda_runtime.h>
#include <cuda_fp16.h>
#include <cstdint>
#include <math.h>

// ---------------- problem constants ----------------
#define TOPK 6
#define NE   64
#define ND   2048
#define NF   1408
#define NFS  2816
#define NTOK 8192
#define NA   (NTOK*TOPK)   // 49152 routed assignments
#define CAP  1536

// ---------------- scratch (device globals) ----------------
__device__ int    g_counts[NE];
__device__ int    g_offsets[NE];
__device__ int    g_cursor[NE];
__device__ int    g_tidx[NA];
__device__ float  g_tw[NA];
__device__ int    g_stok[NA];
__device__ int    g_a2p[NA];
__device__ __half g_xh[(size_t)NTOK * ND];   // x in fp16
__device__ __half g_u [(size_t)NA * NF];     // up proj then act, fp16
__device__ __half g_eo[(size_t)NA * ND];     // expert output rows, fp16
__device__ __half g_su[(size_t)NTOK * NFS];  // shared up then act, fp16
// fp16 weight mirrors
__device__ __half g_wu_h[(size_t)NE * NF * ND];
__device__ __half g_wg_h[(size_t)NE * NF * ND];
__device__ __half g_wd_h[(size_t)NE * ND * NF];
__device__ __half g_shu_h[(size_t)NFS * ND];
__device__ __half g_shg_h[(size_t)NFS * ND];
__device__ __half g_shd_h[(size_t)ND * NFS];

// ---------------- small kernels ----------------
__global__ void zero_kernel() {
    int i = threadIdx.x;
    if (i < NE) { g_counts[i] = 0; g_cursor[i] = 0; }
}

// fp32 -> fp16, 8 elems/thread (2x LDG.128 -> 1x STG.128)
__global__ void cvt_kernel(const float* __restrict__ w, __half* __restrict__ o) {
    size_t i = ((size_t)blockIdx.x * blockDim.x + threadIdx.x) * 8;
    float4 v0 = *(const float4*)(w + i);
    float4 v1 = *(const float4*)(w + i + 4);
    __half2 h0 = __floats2half2_rn(v0.x, v0.y);
    __half2 h1 = __floats2half2_rn(v0.z, v0.w);
    __half2 h2 = __floats2half2_rn(v1.x, v1.y);
    __half2 h3 = __floats2half2_rn(v1.z, v1.w);
    *(uint4*)&o[i] = make_uint4(*(unsigned*)&h0, *(unsigned*)&h1,
                                *(unsigned*)&h2, *(unsigned*)&h3);
}

__global__ void router_kernel(const float* __restrict__ x,
                              const float* __restrict__ gw)
{
    int t = blockIdx.x;
    __shared__ float xs[ND];
    __shared__ float logits[NE];
    const float* xr = x + (size_t)t * ND;
    for (int i = threadIdx.x; i < ND; i += blockDim.x) xs[i] = xr[i];
    __syncthreads();

    int warp = threadIdx.x >> 5, lane = threadIdx.x & 31;
    #pragma unroll
    for (int e8 = 0; e8 < 8; e8++) {
        int e = warp * 8 + e8;
        const float* w = gw + (size_t)e * ND;
        float s = 0.f;
        for (int i = lane; i < ND; i += 32) s += xs[i] * w[i];
        #pragma unroll
        for (int o = 16; o; o >>= 1) s += __shfl_down_sync(0xffffffffu, s, o);
        if (lane == 0) logits[e] = s;
    }
    __syncthreads();

    if (threadIdx.x == 0) {
        int idx6[TOPK]; float val6[TOPK];
        unsigned long long used = 0ull;
        for (int k = 0; k < TOPK; k++) {
            float best = -INFINITY; int bi = 0;
            for (int e = 0; e < NE; e++) {
                if (!((used >> e) & 1ull) && logits[e] > best) { best = logits[e]; bi = e; }
            }
            used |= 1ull << bi; idx6[k] = bi; val6[k] = best;
        }
        float m = val6[0], sum = 0.f, w6[TOPK];
        #pragma unroll
        for (int k = 0; k < TOPK; k++) { w6[k] = expf(val6[k] - m); sum += w6[k]; }
        float inv = 1.f / sum;
        #pragma unroll
        for (int k = 0; k < TOPK; k++) {
            g_tidx[t * TOPK + k] = idx6[k];
            g_tw  [t * TOPK + k] = w6[k] * inv;
            atomicAdd(&g_counts[idx6[k]], 1);
        }
    }
}

__global__ void prefix_kernel() {
    if (threadIdx.x == 0) {
        int acc = 0;
        for (int e = 0; e < NE; e++) { g_offsets[e] = acc; acc += g_counts[e]; }
    }
}

__global__ void scatter_kernel() {
    int a = blockIdx.x * blockDim.x + threadIdx.x;
    if (a >= NA) return;
    int e = g_tidx[a];
    int slot = atomicAdd(&g_cursor[e], 1);
    if (slot < CAP) {
        int p = g_offsets[e] + slot;
        g_stok[p] = a / TOPK;
        g_a2p[a] = p;
    } else {
        g_a2p[a] = -1;
    }
}

// ---------------- all-fp16 tensor-core GEMM (cp.async, BK=32, 4 stages) ------
// C[m][n] = sum_k A[m][k] * B[n][k]; A,B fp16; 128 threads, CTA 128x128,
// warp 64x64 (2x2), 64KB dynamic smem (2 CTAs/SM), ldmatrix frag loads.

__device__ __forceinline__ uint32_t smem_u32(const void* p) {
    uint32_t a;
    asm("{ .reg .u64 t; cvta.to.shared.u64 t, %1; cvt.u32.u64 %0, t; }" : "=r"(a) : "l"(p));
    return a;
}

// byte offset of (row, h), h = 16B column index (0..3), swizzled 64B rows
__device__ __forceinline__ uint32_t swoff(int row, int h) {
    return (uint32_t)(((row >> 1) << 7) +
                      ((((h + ((row & 1) << 2)) ^ ((row >> 1) & 7))) << 4));
}

__device__ __forceinline__ void cp_async16(uint32_t saddr, const void* gptr) {
    asm volatile("cp.async.cg.shared.global [%0], [%1], 16;"
                 :: "r"(saddr), "l"(gptr));
}

__device__ __forceinline__ void ldsm4(unsigned& r0, unsigned& r1, unsigned& r2,
                                      unsigned& r3, uint32_t addr) {
    asm volatile("ldmatrix.sync.aligned.m8n8.x4.shared.b16 {%0,%1,%2,%3}, [%4];"
                 : "=r"(r0), "=r"(r1), "=r"(r2), "=r"(r3) : "r"(addr));
}

__device__ __forceinline__ void mma_f16(float d[4], const unsigned a[4],
                                        const unsigned b[2], const float c[4]) {
    asm volatile(
        "mma.sync.aligned.m16n8k16.row.col.f32.f16.f16.f32 "
        "{%0,%1,%2,%3},{%4,%5,%6,%7},{%8,%9},{%10,%11,%12,%13};\n"
        : "=f"(d[0]), "=f"(d[1]), "=f"(d[2]), "=f"(d[3])
        : "r"(a[0]), "r"(a[1]), "r"(a[2]), "r"(a[3]),
          "r"(b[0]), "r"(b[1]),
          "f"(c[0]), "f"(c[1]), "f"(c[2]), "f"(c[3]));
}

#define MAT_BYTES   8192            // 128 rows x 64B
#define STAGE_BYTES 16384           // A + B
#define NSTAGE      4
#define SMEM_GEMM   (NSTAGE * STAGE_BYTES)   // 65536 (dynamic)

template<int OH, int FUSE>
__global__ __launch_bounds__(128)
void gemm16(const __half* __restrict__ A, int lda,
            const __half* __restrict__ B,
            void* __restrict__ Cv, int ldc,
            int M, int Ntot, int K,
            const int* __restrict__ rowmap,
            const int* __restrict__ offsets,
            const int* __restrict__ counts)
{
    extern __shared__ char sm[];

    int rowbase = 0;
    if (offsets) {
        int e = blockIdx.z;
        rowbase = offsets[e];
        M = min(counts[e], CAP);
        B += (size_t)e * Ntot * K;
    }
    int m0 = blockIdx.y * 128;
    if (m0 >= M) return;
    int n0 = blockIdx.x * 128;

    int tid = threadIdx.x, warp = tid >> 5, lane = tid & 31;
    int wm = warp >> 1, wn = warp & 1;
    int mb = wm * 64, nb = wn * 64;
    int grp = lane >> 2, tig = lane & 3;

    // ---- fill mapping: thread (r0 = tid>>2, q = tid&3) covers rows r0+32i ----
    int r0 = tid >> 2, q = tid & 3;
    int q8 = q * 8;                  // halves offset of this thread's 16B quad
    const __half* ap[4];
    const __half* bp[4];
    uint32_t stoff[4];
    #pragma unroll
    for (int i = 0; i < 4; i++) {
        int row = r0 + 32 * i;
        int ar = min(m0 + row, M - 1);
        int phys = rowmap ? rowmap[rowbase + ar] : (rowbase + ar);
        ap[i] = A + (size_t)phys * lda + q8;
        bp[i] = B + (size_t)(n0 + row) * K + q8;
        stoff[i] = swoff(row, q);
    }

    // ---- ldmatrix lane mapping ----
    int lrow = (lane & 7) + 8 * ((lane >> 3) & 1);
    int lh = (lane >> 4) & 1;
    uint32_t sbase = smem_u32(sm);
    uint32_t aoff[2] = { swoff(mb + lrow, lh), swoff(mb + lrow, 2 + lh) };
    uint32_t boff[2] = { swoff(nb + lrow, lh), swoff(nb + lrow, 2 + lh) };

    float acc[4][8][4];
    #pragma unroll
    for (int mt = 0; mt < 4; mt++)
        #pragma unroll
        for (int nt = 0; nt < 8; nt++)
            #pragma unroll
            for (int j = 0; j < 4; j++) acc[mt][nt][j] = 0.f;

    const int nch = K / 32;

    auto fill = [&](int kc, int s) {
        uint32_t sa = sbase + s * STAGE_BYTES;
        uint32_t sb = sa + MAT_BYTES;
        #pragma unroll
        for (int i = 0; i < 4; i++) {
            cp_async16(sa + stoff[i], ap[i] + kc);
            cp_async16(sb + stoff[i], bp[i] + kc);
        }
        asm volatile("cp.async.commit_group;" ::: "memory");
    };

    // prolog: stages 0,1,2 <- chunks 0,1,2
    fill(0, 0);
    if (nch > 1) fill(32, 1);
    if (nch > 2) fill(64, 2);

    for (int it = 0; it < nch; it++) {
        int s = it & (NSTAGE - 1);
        if (it + 2 < nch)
            asm volatile("cp.async.wait_group 2;" ::: "memory");
        else if (it + 1 < nch)
            asm volatile("cp.async.wait_group 1;" ::: "memory");
        else
            asm volatile("cp.async.wait_group 0;" ::: "memory");
        __syncthreads();

        uint32_t sA = sbase + s * STAGE_BYTES;
        uint32_t sB = sA + MAT_BYTES;
        #pragma unroll
        for (int ks = 0; ks < 2; ks++) {
            unsigned af[4][4], bf[8][2];
            #pragma unroll
            for (int mt = 0; mt < 4; mt++)
                ldsm4(af[mt][0], af[mt][1], af[mt][2], af[mt][3],
                      sA + aoff[ks] + mt * 1024);
            #pragma unroll
            for (int np = 0; np < 4; np++) {
                unsigned t0, t1, t2, t3;
                ldsm4(t0, t1, t2, t3, sB + boff[ks] + np * 1024);
                bf[2 * np][0] = t0;     bf[2 * np][1] = t2;
                bf[2 * np + 1][0] = t1; bf[2 * np + 1][1] = t3;
            }
            #pragma unroll
            for (int mt = 0; mt < 4; mt++)
                #pragma unroll
                for (int nt = 0; nt < 8; nt++)
                    mma_f16(acc[mt][nt], af[mt], bf[nt], acc[mt][nt]);
        }

        if (it + 3 < nch) fill((it + 3) * 32, (it + 3) & (NSTAGE - 1));
    }

    // ---- epilogue ----
    #pragma unroll
    for (int mt = 0; mt < 4; mt++) {
        int row0 = m0 + mb + mt * 16 + grp;
        #pragma unroll
        for (int nt = 0; nt < 8; nt++) {
            int col = n0 + nb + nt * 8 + tig * 2;
            #pragma unroll
            for (int h = 0; h < 2; h++) {
                int row = row0 + h * 8;
                if (row >= M) continue;
                float v0 = acc[mt][nt][2 * h], v1 = acc[mt][nt][2 * h + 1];
                if (OH) {
                    __half2* p = (__half2*)(((__half*)Cv) + (size_t)(rowbase + row) * ldc + col);
                    if (FUSE) {
                        float2 u = __half22float2(*p);
                        v0 = (v0 / (1.f + __expf(-v0))) * u.x;
                        v1 = (v1 / (1.f + __expf(-v1))) * u.y;
                    }
                    *p = __floats2half2_rn(v0, v1);
                } else {
                    float* p = ((float*)Cv) + (size_t)(rowbase + row) * ldc + col;
                    p[0] = v0; p[1] = v1;
                }
            }
        }
    }
}

// out[t][2d..2d+1] += sum_k w(t,k) * eo_h[pos(t,k)][2d..2d+1]
__global__ void combine_kernel(float* __restrict__ out) {
    int t = blockIdx.y;
    int d2 = blockIdx.x * blockDim.x + threadIdx.x;   // half2 index
    float2 s = *(float2*)&out[(size_t)t * ND + 2 * d2];
    #pragma unroll
    for (int k = 0; k < TOPK; k++) {
        int p = g_a2p[t * TOPK + k];
        if (p >= 0) {
            float w = g_tw[t * TOPK + k];
            __half2 h = *(__half2*)&g_eo[(size_t)p * ND + 2 * d2];
            float2 v = __half22float2(h);
            s.x += w * v.x; s.y += w * v.y;
        }
    }
    *(float2*)&out[(size_t)t * ND + 2 * d2] = s;
}

// ---------------- static stream/event resources (host-side only) ----------------
struct AuxRes {
    cudaStream_t s2, s3;
    cudaEvent_t ev_fork, ev_cvt, ev_wup, ev_wgate, ev_wdown, ev_shared;
    AuxRes() {
        cudaStreamCreateWithFlags(&s2, cudaStreamNonBlocking);
        cudaStreamCreateWithFlags(&s3, cudaStreamNonBlocking);
        cudaEventCreateWithFlags(&ev_fork,   cudaEventDisableTiming);
        cudaEventCreateWithFlags(&ev_cvt,    cudaEventDisableTiming);
        cudaEventCreateWithFlags(&ev_wup,    cudaEventDisableTiming);
        cudaEventCreateWithFlags(&ev_wgate,  cudaEventDisableTiming);
        cudaEventCreateWithFlags(&ev_wdown,  cudaEventDisableTiming);
        cudaEventCreateWithFlags(&ev_shared, cudaEventDisableTiming);
    }
};
static AuxRes g_aux;

// ---------------- launch ----------------
extern "C" void kernel_launch(void* const* d_in, const int* in_sizes, int n_in,
                              void* d_out, int out_size)
{
    const float* x       = (const float*)d_in[0];
    const float* gate_w  = (const float*)d_in[1];
    const float* w_gate  = (const float*)d_in[2];
    const float* w_up    = (const float*)d_in[3];
    const float* w_down  = (const float*)d_in[4];
    const float* sh_gate = (const float*)d_in[5];
    const float* sh_up   = (const float*)d_in[6];
    const float* sh_down = (const float*)d_in[7];
    float* out = (float*)d_out;

    void *pxh, *pu, *peo, *psu, *pstok, *poff, *pcnt;
    void *pwu, *pwg, *pwd, *pshu, *pshg, *pshd;
    cudaGetSymbolAddress(&pxh,  g_xh);
    cudaGetSymbolAddress(&pu,   g_u);
    cudaGetSymbolAddress(&peo,  g_eo);
    cudaGetSymbolAddress(&psu,  g_su);
    cudaGetSymbolAddress(&pstok, g_stok);
    cudaGetSymbolAddress(&poff, g_offsets);
    cudaGetSymbolAddress(&pcnt, g_counts);
    cudaGetSymbolAddress(&pwu,  g_wu_h);
    cudaGetSymbolAddress(&pwg,  g_wg_h);
    cudaGetSymbolAddress(&pwd,  g_wd_h);
    cudaGetSymbolAddress(&pshu, g_shu_h);
    cudaGetSymbolAddress(&pshg, g_shg_h);
    cudaGetSymbolAddress(&pshd, g_shd_h);
    __half* xh  = (__half*)pxh;
    __half* ubuf = (__half*)pu;  __half* eo = (__half*)peo;  __half* su = (__half*)psu;
    __half* wu_h = (__half*)pwu; __half* wg_h = (__half*)pwg; __half* wd_h = (__half*)pwd;
    __half* shu_h = (__half*)pshu; __half* shg_h = (__half*)pshg; __half* shd_h = (__half*)pshd;
    int* stok = (int*)pstok;     int* offs = (int*)poff;     int* cnts = (int*)pcnt;

    cudaStream_t s1 = 0;            // main (capture) stream
    cudaStream_t s2 = g_aux.s2;     // x cvt + shared-expert chain
    cudaStream_t s3 = g_aux.s3;     // routed weight conversions

    cudaFuncSetAttribute(gemm16<1,0>, cudaFuncAttributeMaxDynamicSharedMemorySize, SMEM_GEMM);
    cudaFuncSetAttribute(gemm16<1,1>, cudaFuncAttributeMaxDynamicSharedMemorySize, SMEM_GEMM);
    cudaFuncSetAttribute(gemm16<0,0>, cudaFuncAttributeMaxDynamicSharedMemorySize, SMEM_GEMM);

    const unsigned WBLK = (unsigned)((size_t)NE * NF * ND / 8 / 256);
    const unsigned SBLK = (unsigned)((size_t)NFS * ND / 8 / 256);
    const unsigned XBLK = (unsigned)((size_t)NTOK * ND / 8 / 256);

    // ---- fork ----
    cudaEventRecord(g_aux.ev_fork, s1);
    cudaStreamWaitEvent(s2, g_aux.ev_fork, 0);
    cudaStreamWaitEvent(s3, g_aux.ev_fork, 0);

    // ---- stream 3: routed weight conversions (start at t=0) ----
    cvt_kernel<<<WBLK, 256, 0, s3>>>(w_up, wu_h);
    cudaEventRecord(g_aux.ev_wup, s3);
    cvt_kernel<<<WBLK, 256, 0, s3>>>(w_gate, wg_h);
    cudaEventRecord(g_aux.ev_wgate, s3);
    cvt_kernel<<<WBLK, 256, 0, s3>>>(w_down, wd_h);
    cudaEventRecord(g_aux.ev_wdown, s3);

    // ---- stream 2: x cvt + shared weight cvts + shared-expert chain ----
    cvt_kernel<<<XBLK, 256, 0, s2>>>(x, xh);
    cudaEventRecord(g_aux.ev_cvt, s2);
    cvt_kernel<<<SBLK, 256, 0, s2>>>(sh_up,   shu_h);
    cvt_kernel<<<SBLK, 256, 0, s2>>>(sh_gate, shg_h);
    cvt_kernel<<<SBLK, 256, 0, s2>>>(sh_down, shd_h);
    {
        dim3 grid(NFS / 128, NTOK / 128, 1);
        gemm16<1,0><<<grid, 128, SMEM_GEMM, s2>>>(xh, ND, shu_h, su, NFS, NTOK, NFS, ND, nullptr, nullptr, nullptr);
        gemm16<1,1><<<grid, 128, SMEM_GEMM, s2>>>(xh, ND, shg_h, su, NFS, NTOK, NFS, ND, nullptr, nullptr, nullptr);
    }
    {
        dim3 grid(ND / 128, NTOK / 128, 1);
        gemm16<0,0><<<grid, 128, SMEM_GEMM, s2>>>(su, NFS, shd_h, out, ND, NTOK, ND, NFS, nullptr, nullptr, nullptr);
    }
    cudaEventRecord(g_aux.ev_shared, s2);

    // ---- stream 1: router + dispatch + routed chain ----
    zero_kernel<<<1, 64, 0, s1>>>();
    router_kernel<<<NTOK, 256, 0, s1>>>(x, gate_w);
    prefix_kernel<<<1, 1, 0, s1>>>();
    scatter_kernel<<<(NA + 255) / 256, 256, 0, s1>>>();

    cudaStreamWaitEvent(s1, g_aux.ev_cvt, 0);
    cudaStreamWaitEvent(s1, g_aux.ev_wup, 0);
    {
        dim3 grid(NF / 128, CAP / 128, NE);
        gemm16<1,0><<<grid, 128, SMEM_GEMM, s1>>>(xh, ND, wu_h, ubuf, NF, 0, NF, ND, stok, offs, cnts);
        cudaStreamWaitEvent(s1, g_aux.ev_wgate, 0);
        gemm16<1,1><<<grid, 128, SMEM_GEMM, s1>>>(xh, ND, wg_h, ubuf, NF, 0, NF, ND, stok, offs, cnts);
    }
    cudaStreamWaitEvent(s1, g_aux.ev_wdown, 0);
    {
        dim3 grid(ND / 128, CAP / 128, NE);
        gemm16<1,0><<<grid, 128, SMEM_GEMM, s1>>>(ubuf, NF, wd_h, eo, ND, 0, ND, NF, nullptr, offs, cnts);
    }

    // ---- join: combine needs shared-down (out) + routed-down (eo) ----
    cudaStreamWaitEvent(s1, g_aux.ev_shared, 0);
    {
        dim3 grid((ND / 2) / 256, NTOK);
        combine_kernel<<<grid, 256, 0, s1>>>(out);
    }
}